// round 1
// baseline (speedup 1.0000x reference)
#include <cuda_runtime.h>
#include <math.h>

#define Nn 1024
#define Vv 3889
#define NJj 33
#define NBb 41
#define M3 11667   // V*3

// ---------------- scratch (static device allocations; no runtime alloc) ----
__device__ float g_vshaped[Nn * M3];        // ~48 MB
__device__ float g_A[Nn * 400];             // per-n 33x12 relative transforms (stride 400 for f4 align)
__device__ float g_SJ[NBb * NJj * 3];       // shapedirs folded through J_regressor
__device__ float g_Jt[NJj * 3];             // template joints
__device__ float g_jpart[Nn * 32 * 99];     // per-chunk joint partials (deterministic reduce)

// scal code per (joint, axis): 0 -> 1.0, 1..4 -> exp(betas_logscale[c-1])
__constant__ unsigned char c_sc[99] = {
    0,0,0, 0,0,0, 0,0,0, 0,0,0, 0,0,0, 0,0,0, 0,0,0,          // joints 0-6
    2,2,1, 2,2,1, 2,2,1, 2,2,1, 2,2,1, 2,2,1, 2,2,1, 2,2,1,   // 7-14 (legs)
    0,0,0, 0,0,0,                                              // 15,16
    2,2,1, 2,2,1, 2,2,1, 2,2,1, 2,2,1, 2,2,1, 2,2,1, 2,2,1,   // 17-24 (legs)
    3,4,4, 3,4,4, 3,4,4, 3,4,4, 3,4,4, 3,4,4, 3,4,4,          // 25-31 (tail)
    0,0,0                                                      // 32
};

// ---------------- K1: SJ[k,j,:] = sum_v sd[k,v,:]*Jr[v,j]; Jt[j,:] = sum_v vt[v,:]*Jr[v,j]
__global__ void k_sj(const float* __restrict__ sd, const float* __restrict__ vt,
                     const float* __restrict__ jr) {
    int k = blockIdx.x;   // 0..41 (41 == v_template row)
    int j = blockIdx.y;   // 0..32
    const float* src = (k < NBb) ? (sd + k * M3) : vt;
    float a0 = 0.f, a1 = 0.f, a2 = 0.f;
    for (int v = threadIdx.x; v < Vv; v += 128) {
        float w = jr[v * NJj + j];
        a0 = fmaf(w, src[v * 3 + 0], a0);
        a1 = fmaf(w, src[v * 3 + 1], a1);
        a2 = fmaf(w, src[v * 3 + 2], a2);
    }
    #pragma unroll
    for (int off = 16; off; off >>= 1) {
        a0 += __shfl_down_sync(0xffffffffu, a0, off);
        a1 += __shfl_down_sync(0xffffffffu, a1, off);
        a2 += __shfl_down_sync(0xffffffffu, a2, off);
    }
    __shared__ float r0[4], r1[4], r2[4];
    int wid = threadIdx.x >> 5, lane = threadIdx.x & 31;
    if (lane == 0) { r0[wid] = a0; r1[wid] = a1; r2[wid] = a2; }
    __syncthreads();
    if (threadIdx.x == 0) {
        a0 = r0[0] + r0[1] + r0[2] + r0[3];
        a1 = r1[0] + r1[1] + r1[2] + r1[3];
        a2 = r2[0] + r2[1] + r2[2] + r2[3];
        float* dst = (k < NBb) ? (g_SJ + k * 99 + j * 3) : (g_Jt + j * 3);
        dst[0] = a0; dst[1] = a1; dst[2] = a2;
    }
}

// ---------------- K2: v_shaped = v_template + beta @ shapedirs  (16 n per block)
__global__ void k_vshape(const float* __restrict__ beta, const float* __restrict__ sd,
                         const float* __restrict__ vt) {
    __shared__ float bs[16 * NBb];
    int n0 = blockIdx.y * 16;
    int m = blockIdx.x * 128 + threadIdx.x;
    for (int i = threadIdx.x; i < 16 * NBb; i += 128)
        bs[i] = beta[(n0 + i / NBb) * NBb + (i % NBb)];
    __syncthreads();
    if (m >= M3) return;
    float base = vt[m];
    float acc[16];
    #pragma unroll
    for (int i = 0; i < 16; i++) acc[i] = base;
    #pragma unroll 1
    for (int k = 0; k < NBb; k++) {
        float s = sd[k * M3 + m];
        #pragma unroll
        for (int i = 0; i < 16; i++) acc[i] = fmaf(bs[i * NBb + k], s, acc[i]);
    }
    #pragma unroll
    for (int i = 0; i < 16; i++) g_vshaped[(n0 + i) * M3 + m] = acc[i];
}

// ---------------- K3: rodrigues + kinematic chain; one thread per n -------
__device__ __forceinline__ void rodrigues(const float* __restrict__ th, float R[9]) {
    float t0 = th[0], t1 = th[1], t2 = th[2];
    float a0 = t0 + 1e-8f, a1 = t1 + 1e-8f, a2 = t2 + 1e-8f;
    float ang = sqrtf(a0 * a0 + a1 * a1 + a2 * a2);
    float inv = 1.f / ang;
    float r0 = t0 * inv, r1 = t1 * inv, r2 = t2 * inv;
    float s, c;
    sincosf(ang, &s, &c);
    float oc = 1.f - c;
    R[0] = c + oc * r0 * r0;       R[1] = oc * r0 * r1 - s * r2;  R[2] = oc * r0 * r2 + s * r1;
    R[3] = oc * r0 * r1 + s * r2;  R[4] = c + oc * r1 * r1;       R[5] = oc * r1 * r2 - s * r0;
    R[6] = oc * r0 * r2 - s * r1;  R[7] = oc * r1 * r2 + s * r0;  R[8] = c + oc * r2 * r2;
}

__global__ void k_chain(const float* __restrict__ beta, const float* __restrict__ theta,
                        const float* __restrict__ bls) {
    int n = blockIdx.x * 32 + threadIdx.x;
    if (n >= Nn) return;
    float b[NBb];
    #pragma unroll
    for (int k = 0; k < NBb; k++) b[k] = beta[n * NBb + k];
    float e[5];
    e[0] = 1.f;
    e[1] = expf(bls[n * 6 + 0]);
    e[2] = expf(bls[n * 6 + 1]);
    e[3] = expf(bls[n * 6 + 2]);
    e[4] = expf(bls[n * 6 + 3]);
    const float* th = theta + n * 105;
    float* Aout = g_A + n * 400;

    float Rp[9], tp[3], Jp[3], sp0, sp1, sp2;

    // joint 0
    {
        float J0[3];
        J0[0] = g_Jt[0]; J0[1] = g_Jt[1]; J0[2] = g_Jt[2];
        #pragma unroll
        for (int k = 0; k < NBb; k++) {
            const float* s = g_SJ + k * 99;
            J0[0] = fmaf(b[k], s[0], J0[0]);
            J0[1] = fmaf(b[k], s[1], J0[1]);
            J0[2] = fmaf(b[k], s[2], J0[2]);
        }
        float R[9];
        rodrigues(th, R);
        #pragma unroll
        for (int r = 0; r < 3; r++) {
            Aout[r * 4 + 0] = R[r * 3 + 0];
            Aout[r * 4 + 1] = R[r * 3 + 1];
            Aout[r * 4 + 2] = R[r * 3 + 2];
            float ib = R[r * 3 + 0] * J0[0] + R[r * 3 + 1] * J0[1] + R[r * 3 + 2] * J0[2];
            Aout[r * 4 + 3] = J0[r] - ib;
        }
        #pragma unroll
        for (int q = 0; q < 9; q++) Rp[q] = R[q];
        tp[0] = J0[0]; tp[1] = J0[1]; tp[2] = J0[2];
        Jp[0] = J0[0]; Jp[1] = J0[1]; Jp[2] = J0[2];
        sp0 = 1.f; sp1 = 1.f; sp2 = 1.f;
    }

    #pragma unroll 1
    for (int i = 1; i < NJj; i++) {
        float Ji[3];
        Ji[0] = g_Jt[i * 3 + 0]; Ji[1] = g_Jt[i * 3 + 1]; Ji[2] = g_Jt[i * 3 + 2];
        #pragma unroll
        for (int k = 0; k < NBb; k++) {
            const float* s = g_SJ + k * 99 + i * 3;
            Ji[0] = fmaf(b[k], s[0], Ji[0]);
            Ji[1] = fmaf(b[k], s[1], Ji[1]);
            Ji[2] = fmaf(b[k], s[2], Ji[2]);
        }
        float Ri[9];
        rodrigues(th + i * 3, Ri);
        float s0 = e[c_sc[i * 3 + 0]], s1 = e[c_sc[i * 3 + 1]], s2 = e[c_sc[i * 3 + 2]];
        float ip0 = 1.f / sp0, ip1 = 1.f / sp1, ip2 = 1.f / sp2;
        float Rn[9], tn[3];
        #pragma unroll
        for (int r = 0; r < 3; r++) {
            float m0 = Rp[r * 3 + 0] * ip0;
            float m1 = Rp[r * 3 + 1] * ip1;
            float m2 = Rp[r * 3 + 2] * ip2;
            Rn[r * 3 + 0] = (m0 * Ri[0] + m1 * Ri[3] + m2 * Ri[6]) * s0;
            Rn[r * 3 + 1] = (m0 * Ri[1] + m1 * Ri[4] + m2 * Ri[7]) * s1;
            Rn[r * 3 + 2] = (m0 * Ri[2] + m1 * Ri[5] + m2 * Ri[8]) * s2;
        }
        float d0 = Ji[0] - Jp[0], d1 = Ji[1] - Jp[1], d2 = Ji[2] - Jp[2];
        #pragma unroll
        for (int r = 0; r < 3; r++)
            tn[r] = Rp[r * 3 + 0] * d0 + Rp[r * 3 + 1] * d1 + Rp[r * 3 + 2] * d2 + tp[r];
        float* Ao = Aout + i * 12;
        #pragma unroll
        for (int r = 0; r < 3; r++) {
            Ao[r * 4 + 0] = Rn[r * 3 + 0];
            Ao[r * 4 + 1] = Rn[r * 3 + 1];
            Ao[r * 4 + 2] = Rn[r * 3 + 2];
            float ib = Rn[r * 3 + 0] * Ji[0] + Rn[r * 3 + 1] * Ji[1] + Rn[r * 3 + 2] * Ji[2];
            Ao[r * 4 + 3] = tn[r] - ib;
        }
        #pragma unroll
        for (int q = 0; q < 9; q++) Rp[q] = Rn[q];
        tp[0] = tn[0]; tp[1] = tn[1]; tp[2] = tn[2];
        Jp[0] = Ji[0]; Jp[1] = Ji[1]; Jp[2] = Ji[2];
        sp0 = s0; sp1 = s1; sp2 = s2;
    }
}

// ---------------- K4: skinning + fused joint partials. block = (chunk, n) --
__global__ void k_skin(const float* __restrict__ wts, const float* __restrict__ jr,
                       const float* __restrict__ trans,
                       float* __restrict__ outv, float* __restrict__ outj) {
    __shared__ float4 As4[100];
    __shared__ float sw[256 * 33];   // weights, then reused for J_regressor
    __shared__ float4 vs4[256];
    int chunk = blockIdx.x;
    int n = blockIdx.y;
    int v0 = chunk * 256;
    int tx = threadIdx.x;
    int cnt = min(256, Vv - v0);
    float* As = (float*)As4;
    for (int i = tx; i < 396; i += 256) As[i] = g_A[n * 400 + i];
    for (int i = tx; i < cnt * 33; i += 256) sw[i] = wts[v0 * 33 + i];
    __syncthreads();

    int v = v0 + tx;
    bool valid = tx < cnt;
    float ox = 0.f, oy = 0.f, oz = 0.f;
    if (valid) {
        const float* vp = g_vshaped + n * M3 + v * 3;
        float vx = vp[0], vy = vp[1], vz = vp[2];
        float4 T0 = {0, 0, 0, 0}, T1 = {0, 0, 0, 0}, T2 = {0, 0, 0, 0};
        #pragma unroll 1
        for (int j = 0; j < 33; j++) {
            float w = sw[tx * 33 + j];
            float4 a0 = As4[j * 3 + 0];
            float4 a1 = As4[j * 3 + 1];
            float4 a2 = As4[j * 3 + 2];
            T0.x = fmaf(w, a0.x, T0.x); T0.y = fmaf(w, a0.y, T0.y);
            T0.z = fmaf(w, a0.z, T0.z); T0.w = fmaf(w, a0.w, T0.w);
            T1.x = fmaf(w, a1.x, T1.x); T1.y = fmaf(w, a1.y, T1.y);
            T1.z = fmaf(w, a1.z, T1.z); T1.w = fmaf(w, a1.w, T1.w);
            T2.x = fmaf(w, a2.x, T2.x); T2.y = fmaf(w, a2.y, T2.y);
            T2.z = fmaf(w, a2.z, T2.z); T2.w = fmaf(w, a2.w, T2.w);
        }
        ox = fmaf(T0.x, vx, fmaf(T0.y, vy, fmaf(T0.z, vz, T0.w))) + trans[n * 3 + 0];
        oy = fmaf(T1.x, vx, fmaf(T1.y, vy, fmaf(T1.z, vz, T1.w))) + trans[n * 3 + 1];
        oz = fmaf(T2.x, vx, fmaf(T2.y, vy, fmaf(T2.z, vz, T2.w))) + trans[n * 3 + 2];
        float* ov = outv + n * M3 + v * 3;
        ov[0] = ox; ov[1] = oy; ov[2] = oz;
        int ei = -1;
        if (v == 1863) ei = 0; else if (v == 26) ei = 1; else if (v == 2124) ei = 2;
        else if (v == 150) ei = 3; else if (v == 3055) ei = 4; else if (v == 1097) ei = 5;
        if (ei >= 0) {
            float* oj = outj + n * 117 + (33 + ei) * 3;
            oj[0] = ox; oj[1] = oy; oj[2] = oz;
        }
    }
    __syncthreads();   // done reading weights from sw
    for (int i = tx; i < cnt * 33; i += 256) sw[i] = jr[v0 * 33 + i];
    vs4[tx] = make_float4(ox, oy, oz, 0.f);
    __syncthreads();
    if (tx < 198) {
        int g = tx / 99, t = tx - g * 99;
        int j = t / 3, a = t - j * 3;
        int vs = g * 128, ve = min(cnt, (g + 1) * 128);
        float acc = 0.f;
        const float* vf = (const float*)vs4;
        for (int vv = vs; vv < ve; vv++)
            acc = fmaf(vf[vv * 4 + a], sw[vv * 33 + j], acc);
        g_jpart[(n * 32 + chunk * 2 + g) * 99 + t] = acc;
    }
}

// ---------------- K5: deterministic joint reduce --------------------------
__global__ void k_jred(float* __restrict__ outj) {
    int idx = blockIdx.x * 256 + threadIdx.x;
    if (idx >= Nn * 99) return;
    int n = idx / 99, t = idx - n * 99;
    const float* p = g_jpart + n * 32 * 99 + t;
    float acc = 0.f;
    #pragma unroll
    for (int c = 0; c < 32; c++) acc += p[c * 99];
    outj[n * 117 + t] = acc;
}

// ---------------- launch ---------------------------------------------------
extern "C" void kernel_launch(void* const* d_in, const int* in_sizes, int n_in,
                              void* d_out, int out_size) {
    const float* beta  = (const float*)d_in[0];
    const float* theta = (const float*)d_in[1];
    const float* trans = (const float*)d_in[2];
    const float* bls   = (const float*)d_in[3];
    const float* sd    = (const float*)d_in[4];
    const float* vt    = (const float*)d_in[5];
    const float* jreg  = (const float*)d_in[6];
    // d_in[7] = posedirs: multiplied by exact zeros in the reference -> unused
    const float* wts   = (const float*)d_in[8];
    float* outv = (float*)d_out;
    float* outj = outv + (size_t)Nn * M3;

    k_sj    <<<dim3(42, 33), 128>>>(sd, vt, jreg);
    k_vshape<<<dim3(92, 64), 128>>>(beta, sd, vt);
    k_chain <<<32, 32>>>(beta, theta, bls);
    k_skin  <<<dim3(16, Nn), 256>>>(wts, jreg, trans, outv, outj);
    k_jred  <<<(Nn * 99 + 255) / 256, 256>>>(outj);
}

// round 2
// speedup vs baseline: 1.0551x; 1.0551x over previous
#include <cuda_runtime.h>
#include <math.h>

#define Nn 1024
#define Vv 3889
#define NJj 33
#define NBb 41
#define M3 11667   // V*3

// ---------------- scratch (static device allocations) ----------------------
__device__ float g_vshaped[Nn * M3];        // ~48 MB
__device__ float g_A[Nn * 400];             // per-n 33x12 transforms (stride 400)
__device__ float g_SJ[NBb * 99];            // shapedirs folded through J_regressor
__device__ float g_Jt[99];                  // template joints
__device__ float g_jpart[Nn * 16 * 99];     // per-chunk joint partials

// scal code per (joint, axis): 0 -> 1.0, 1..4 -> exp(betas_logscale[c-1])
__constant__ unsigned char c_sc[99] = {
    0,0,0, 0,0,0, 0,0,0, 0,0,0, 0,0,0, 0,0,0, 0,0,0,
    2,2,1, 2,2,1, 2,2,1, 2,2,1, 2,2,1, 2,2,1, 2,2,1, 2,2,1,
    0,0,0, 0,0,0,
    2,2,1, 2,2,1, 2,2,1, 2,2,1, 2,2,1, 2,2,1, 2,2,1, 2,2,1,
    3,4,4, 3,4,4, 3,4,4, 3,4,4, 3,4,4, 3,4,4, 3,4,4,
    0,0,0
};

// ---------------- packed f32x2 helpers -------------------------------------
typedef unsigned long long u64;
__device__ __forceinline__ u64 pk2(float a, float b) {
    u64 r; asm("mov.b64 %0,{%1,%2};" : "=l"(r) : "f"(a), "f"(b)); return r;
}
__device__ __forceinline__ void upk2(u64 v, float& a, float& b) {
    asm("mov.b64 {%0,%1},%2;" : "=f"(a), "=f"(b) : "l"(v));
}
__device__ __forceinline__ u64 fma2(u64 a, u64 b, u64 c) {
    u64 r; asm("fma.rn.f32x2 %0,%1,%2,%3;" : "=l"(r) : "l"(a), "l"(b), "l"(c)); return r;
}

// ---------------- K1: fold shapedirs/v_template through J_regressor --------
__global__ void k_sj(const float* __restrict__ sd, const float* __restrict__ vt,
                     const float* __restrict__ jr) {
    int k = blockIdx.x;   // 0..41 (41 == v_template row)
    int j = blockIdx.y;
    const float* src = (k < NBb) ? (sd + k * M3) : vt;
    float a0 = 0.f, a1 = 0.f, a2 = 0.f;
    for (int v = threadIdx.x; v < Vv; v += 128) {
        float w = jr[v * NJj + j];
        a0 = fmaf(w, src[v * 3 + 0], a0);
        a1 = fmaf(w, src[v * 3 + 1], a1);
        a2 = fmaf(w, src[v * 3 + 2], a2);
    }
    #pragma unroll
    for (int off = 16; off; off >>= 1) {
        a0 += __shfl_down_sync(0xffffffffu, a0, off);
        a1 += __shfl_down_sync(0xffffffffu, a1, off);
        a2 += __shfl_down_sync(0xffffffffu, a2, off);
    }
    __shared__ float r0[4], r1[4], r2[4];
    int wid = threadIdx.x >> 5, lane = threadIdx.x & 31;
    if (lane == 0) { r0[wid] = a0; r1[wid] = a1; r2[wid] = a2; }
    __syncthreads();
    if (threadIdx.x == 0) {
        a0 = r0[0] + r0[1] + r0[2] + r0[3];
        a1 = r1[0] + r1[1] + r1[2] + r1[3];
        a2 = r2[0] + r2[1] + r2[2] + r2[3];
        float* dst = (k < NBb) ? (g_SJ + k * 99 + j * 3) : (g_Jt + j * 3);
        dst[0] = a0; dst[1] = a1; dst[2] = a2;
    }
}

// ---------------- K2: v_shaped = v_template + beta @ shapedirs -------------
// 32 n per block packed as 16 f32x2 lanes; 2 m per thread (m, m+128).
__global__ void __launch_bounds__(128) k_vshape(const float* __restrict__ beta,
                                                const float* __restrict__ sd,
                                                const float* __restrict__ vt) {
    __shared__ u64 bs2[NBb * 16];
    int n0 = blockIdx.y * 32;
    int tx = threadIdx.x;
    for (int i = tx; i < NBb * 16; i += 128) {
        int k = i >> 4, p = i & 15;
        bs2[i] = pk2(beta[(n0 + 2 * p) * NBb + k], beta[(n0 + 2 * p + 1) * NBb + k]);
    }
    __syncthreads();
    int m0 = blockIdx.x * 256 + tx;
    int m1 = m0 + 128;
    bool g0 = m0 < M3, g1 = m1 < M3;
    float base0 = g0 ? vt[m0] : 0.f;
    float base1 = g1 ? vt[m1] : 0.f;
    u64 acc0[16], acc1[16];
    u64 b0 = pk2(base0, base0), b1 = pk2(base1, base1);
    #pragma unroll
    for (int p = 0; p < 16; p++) { acc0[p] = b0; acc1[p] = b1; }
    #pragma unroll 1
    for (int k = 0; k < NBb; k++) {
        float s0 = g0 ? sd[k * M3 + m0] : 0.f;
        float s1 = g1 ? sd[k * M3 + m1] : 0.f;
        u64 sp0 = pk2(s0, s0), sp1 = pk2(s1, s1);
        #pragma unroll
        for (int p = 0; p < 16; p++) {
            u64 bp = bs2[k * 16 + p];
            acc0[p] = fma2(bp, sp0, acc0[p]);
            acc1[p] = fma2(bp, sp1, acc1[p]);
        }
    }
    #pragma unroll
    for (int p = 0; p < 16; p++) {
        float lo, hi;
        if (g0) {
            upk2(acc0[p], lo, hi);
            g_vshaped[(size_t)(n0 + 2 * p) * M3 + m0] = lo;
            g_vshaped[(size_t)(n0 + 2 * p + 1) * M3 + m0] = hi;
        }
        if (g1) {
            upk2(acc1[p], lo, hi);
            g_vshaped[(size_t)(n0 + 2 * p) * M3 + m1] = lo;
            g_vshaped[(size_t)(n0 + 2 * p + 1) * M3 + m1] = hi;
        }
    }
}

// ---------------- K3: rodrigues + kinematic chain --------------------------
__device__ __forceinline__ void rodrigues(const float* __restrict__ th, float R[9]) {
    float t0 = th[0], t1 = th[1], t2 = th[2];
    float a0 = t0 + 1e-8f, a1 = t1 + 1e-8f, a2 = t2 + 1e-8f;
    float ang = sqrtf(a0 * a0 + a1 * a1 + a2 * a2);
    float inv = 1.f / ang;
    float r0 = t0 * inv, r1 = t1 * inv, r2 = t2 * inv;
    float s, c;
    sincosf(ang, &s, &c);
    float oc = 1.f - c;
    R[0] = c + oc * r0 * r0;       R[1] = oc * r0 * r1 - s * r2;  R[2] = oc * r0 * r2 + s * r1;
    R[3] = oc * r0 * r1 + s * r2;  R[4] = c + oc * r1 * r1;       R[5] = oc * r1 * r2 - s * r0;
    R[6] = oc * r0 * r2 - s * r1;  R[7] = oc * r1 * r2 + s * r0;  R[8] = c + oc * r2 * r2;
}

__global__ void k_chain(const float* __restrict__ beta, const float* __restrict__ theta,
                        const float* __restrict__ bls) {
    int n = blockIdx.x * 32 + threadIdx.x;
    if (n >= Nn) return;
    float b[NBb];
    #pragma unroll
    for (int k = 0; k < NBb; k++) b[k] = beta[n * NBb + k];
    float e[5];
    e[0] = 1.f;
    e[1] = expf(bls[n * 6 + 0]);
    e[2] = expf(bls[n * 6 + 1]);
    e[3] = expf(bls[n * 6 + 2]);
    e[4] = expf(bls[n * 6 + 3]);
    const float* th = theta + n * 105;
    float* Aout = g_A + n * 400;

    float Rp[9], tp[3], Jp[3], sp0, sp1, sp2;
    {
        float J0[3] = {g_Jt[0], g_Jt[1], g_Jt[2]};
        #pragma unroll
        for (int k = 0; k < NBb; k++) {
            const float* s = g_SJ + k * 99;
            J0[0] = fmaf(b[k], s[0], J0[0]);
            J0[1] = fmaf(b[k], s[1], J0[1]);
            J0[2] = fmaf(b[k], s[2], J0[2]);
        }
        float R[9];
        rodrigues(th, R);
        #pragma unroll
        for (int r = 0; r < 3; r++) {
            Aout[r * 4 + 0] = R[r * 3 + 0];
            Aout[r * 4 + 1] = R[r * 3 + 1];
            Aout[r * 4 + 2] = R[r * 3 + 2];
            float ib = R[r * 3 + 0] * J0[0] + R[r * 3 + 1] * J0[1] + R[r * 3 + 2] * J0[2];
            Aout[r * 4 + 3] = J0[r] - ib;
        }
        #pragma unroll
        for (int q = 0; q < 9; q++) Rp[q] = R[q];
        tp[0] = J0[0]; tp[1] = J0[1]; tp[2] = J0[2];
        Jp[0] = J0[0]; Jp[1] = J0[1]; Jp[2] = J0[2];
        sp0 = 1.f; sp1 = 1.f; sp2 = 1.f;
    }
    #pragma unroll 1
    for (int i = 1; i < NJj; i++) {
        float Ji[3] = {g_Jt[i * 3 + 0], g_Jt[i * 3 + 1], g_Jt[i * 3 + 2]};
        #pragma unroll
        for (int k = 0; k < NBb; k++) {
            const float* s = g_SJ + k * 99 + i * 3;
            Ji[0] = fmaf(b[k], s[0], Ji[0]);
            Ji[1] = fmaf(b[k], s[1], Ji[1]);
            Ji[2] = fmaf(b[k], s[2], Ji[2]);
        }
        float Ri[9];
        rodrigues(th + i * 3, Ri);
        float s0 = e[c_sc[i * 3 + 0]], s1 = e[c_sc[i * 3 + 1]], s2 = e[c_sc[i * 3 + 2]];
        float ip0 = 1.f / sp0, ip1 = 1.f / sp1, ip2 = 1.f / sp2;
        float Rn[9], tn[3];
        #pragma unroll
        for (int r = 0; r < 3; r++) {
            float m0 = Rp[r * 3 + 0] * ip0;
            float m1 = Rp[r * 3 + 1] * ip1;
            float m2 = Rp[r * 3 + 2] * ip2;
            Rn[r * 3 + 0] = (m0 * Ri[0] + m1 * Ri[3] + m2 * Ri[6]) * s0;
            Rn[r * 3 + 1] = (m0 * Ri[1] + m1 * Ri[4] + m2 * Ri[7]) * s1;
            Rn[r * 3 + 2] = (m0 * Ri[2] + m1 * Ri[5] + m2 * Ri[8]) * s2;
        }
        float d0 = Ji[0] - Jp[0], d1 = Ji[1] - Jp[1], d2 = Ji[2] - Jp[2];
        #pragma unroll
        for (int r = 0; r < 3; r++)
            tn[r] = Rp[r * 3 + 0] * d0 + Rp[r * 3 + 1] * d1 + Rp[r * 3 + 2] * d2 + tp[r];
        float* Ao = Aout + i * 12;
        #pragma unroll
        for (int r = 0; r < 3; r++) {
            Ao[r * 4 + 0] = Rn[r * 3 + 0];
            Ao[r * 4 + 1] = Rn[r * 3 + 1];
            Ao[r * 4 + 2] = Rn[r * 3 + 2];
            float ib = Rn[r * 3 + 0] * Ji[0] + Rn[r * 3 + 1] * Ji[1] + Rn[r * 3 + 2] * Ji[2];
            Ao[r * 4 + 3] = tn[r] - ib;
        }
        #pragma unroll
        for (int q = 0; q < 9; q++) Rp[q] = Rn[q];
        tp[0] = tn[0]; tp[1] = tn[1]; tp[2] = tn[2];
        Jp[0] = Ji[0]; Jp[1] = Ji[1]; Jp[2] = Ji[2];
        sp0 = s0; sp1 = s1; sp2 = s2;
    }
}

// ---------------- K4: skinning + fused joint partials ----------------------
// block = 128 threads, chunk = 256 verts (thread handles v0+tx and v0+tx+128)
__device__ __forceinline__ int eidx(int v) {
    if (v == 1863) return 0;
    if (v == 26)   return 1;
    if (v == 2124) return 2;
    if (v == 150)  return 3;
    if (v == 3055) return 4;
    if (v == 1097) return 5;
    return -1;
}

__global__ void __launch_bounds__(128) k_skin(const float* __restrict__ wts,
                                              const float* __restrict__ jr,
                                              const float* __restrict__ trans,
                                              float* __restrict__ outv,
                                              float* __restrict__ outj) {
    __shared__ float As[400];       // 33x12 transforms
    __shared__ float sw[8514];      // weights [256][33], reused as jrT [33][258]
    __shared__ float vsT[3 * 264];  // verts transposed [a][256+pad]
    int chunk = blockIdx.x, n = blockIdx.y;
    int v0 = chunk * 256;
    int tx = threadIdx.x;
    int cnt = min(256, Vv - v0);
    int wtot = cnt * 33;
    for (int i = tx; i < 396; i += 128) As[i] = g_A[n * 400 + i];
    for (int i = tx; i < 8448; i += 128) sw[i] = (i < wtot) ? wts[v0 * 33 + i] : 0.f;
    __syncthreads();

    int va = v0 + tx, vb = va + 128;
    bool ga = tx < cnt, gb = tx + 128 < cnt;
    const float* vpa = g_vshaped + (size_t)n * M3 + va * 3;
    float ax = ga ? vpa[0] : 0.f, ay = ga ? vpa[1] : 0.f, az = ga ? vpa[2] : 0.f;
    float bx = gb ? vpa[384] : 0.f, by = gb ? vpa[385] : 0.f, bz = gb ? vpa[386] : 0.f;

    u64 Aa[3][2] = {}, Ab[3][2] = {};
    const ulonglong2* As2 = (const ulonglong2*)As;
    #pragma unroll 11
    for (int j = 0; j < 33; j++) {
        float wa = sw[tx * 33 + j];
        float wb = sw[(tx + 128) * 33 + j];
        u64 wpa = pk2(wa, wa), wpb = pk2(wb, wb);
        #pragma unroll
        for (int r = 0; r < 3; r++) {
            ulonglong2 arow = As2[j * 3 + r];
            Aa[r][0] = fma2(wpa, arow.x, Aa[r][0]);
            Aa[r][1] = fma2(wpa, arow.y, Aa[r][1]);
            Ab[r][0] = fma2(wpb, arow.x, Ab[r][0]);
            Ab[r][1] = fma2(wpb, arow.y, Ab[r][1]);
        }
    }
    float tr[3] = {trans[n * 3 + 0], trans[n * 3 + 1], trans[n * 3 + 2]};
    float oa[3], ob[3];
    #pragma unroll
    for (int r = 0; r < 3; r++) {
        float p, q, s, t;
        upk2(Aa[r][0], p, q); upk2(Aa[r][1], s, t);
        oa[r] = fmaf(p, ax, fmaf(q, ay, fmaf(s, az, t))) + tr[r];
        upk2(Ab[r][0], p, q); upk2(Ab[r][1], s, t);
        ob[r] = fmaf(p, bx, fmaf(q, by, fmaf(s, bz, t))) + tr[r];
    }
    if (ga) {
        float* o = outv + (size_t)n * M3 + va * 3;
        o[0] = oa[0]; o[1] = oa[1]; o[2] = oa[2];
        int ei = eidx(va);
        if (ei >= 0) {
            float* oj = outj + n * 117 + (33 + ei) * 3;
            oj[0] = oa[0]; oj[1] = oa[1]; oj[2] = oa[2];
        }
    }
    if (gb) {
        float* o = outv + (size_t)n * M3 + vb * 3;
        o[0] = ob[0]; o[1] = ob[1]; o[2] = ob[2];
        int ei = eidx(vb);
        if (ei >= 0) {
            float* oj = outj + n * 117 + (33 + ei) * 3;
            oj[0] = ob[0]; oj[1] = ob[1]; oj[2] = ob[2];
        }
    }
    #pragma unroll
    for (int r = 0; r < 3; r++) {
        vsT[r * 264 + tx]       = ga ? oa[r] : 0.f;
        vsT[r * 264 + tx + 128] = gb ? ob[r] : 0.f;
    }
    __syncthreads();   // weights reads done; vsT populated
    // stage J_regressor transposed into sw: jrT[j][v], rows padded to 258
    for (int i = tx; i < 8448; i += 128) {
        int v = i / 33, j = i - v * 33;
        float val = (v < cnt) ? jr[v0 * 33 + i] : 0.f;
        sw[j * 258 + v] = val;
    }
    __syncthreads();
    if (tx < 99) {
        int j = tx / 3, a = tx - j * 3;
        const u64* vp = (const u64*)&vsT[a * 264];
        const u64* jp = (const u64*)&sw[j * 258];
        u64 acc = 0ull;
        #pragma unroll 8
        for (int h = 0; h < 128; h++) acc = fma2(vp[h], jp[h], acc);
        float lo, hi; upk2(acc, lo, hi);
        g_jpart[((size_t)n * 16 + chunk) * 99 + tx] = lo + hi;
    }
}

// ---------------- K5: deterministic joint reduce ---------------------------
__global__ void k_jred(float* __restrict__ outj) {
    int idx = blockIdx.x * 256 + threadIdx.x;
    if (idx >= Nn * 99) return;
    int n = idx / 99, t = idx - n * 99;
    const float* p = g_jpart + (size_t)n * 16 * 99 + t;
    float acc = 0.f;
    #pragma unroll
    for (int c = 0; c < 16; c++) acc += p[c * 99];
    outj[n * 117 + t] = acc;
}

// ---------------- launch ---------------------------------------------------
extern "C" void kernel_launch(void* const* d_in, const int* in_sizes, int n_in,
                              void* d_out, int out_size) {
    const float* beta  = (const float*)d_in[0];
    const float* theta = (const float*)d_in[1];
    const float* trans = (const float*)d_in[2];
    const float* bls   = (const float*)d_in[3];
    const float* sd    = (const float*)d_in[4];
    const float* vt    = (const float*)d_in[5];
    const float* jreg  = (const float*)d_in[6];
    // d_in[7] = posedirs: multiplied by exact zeros in the reference -> unused
    const float* wts   = (const float*)d_in[8];
    float* outv = (float*)d_out;
    float* outj = outv + (size_t)Nn * M3;

    k_sj    <<<dim3(42, 33), 128>>>(sd, vt, jreg);
    k_vshape<<<dim3(46, 32), 128>>>(beta, sd, vt);
    k_chain <<<32, 32>>>(beta, theta, bls);
    k_skin  <<<dim3(16, Nn), 128>>>(wts, jreg, trans, outv, outj);
    k_jred  <<<(Nn * 99 + 255) / 256, 256>>>(outj);
}